// round 6
// baseline (speedup 1.0000x reference)
#include <cuda_runtime.h>
#include <cuda_bf16.h>
#include <cstdint>

#define B_TOTAL  16384
#define K_DIM    4096
#define F_EPS    1.1920929e-07f

#define ROWS_CTA 8
#define KT       512
#define NTILES   (K_DIM / KT)            // 8
// x: 8 rows resident, padded stride 4104 floats (16416 B, %128B = 8 words -> 2-phase LDS.64)
#define SXROW_F  4104
#define SXROW_B  (SXROW_F * 4)           // 16416
#define X_REGION_B (ROWS_CTA * SXROW_B)  // 131328
// W: 32 rows x KT bf16, padded stride 1040 B, double buffered
#define SWROW_B  1040
#define W_STAGE_B (32 * SWROW_B)         // 33280
#define SMEM_B   (X_REGION_B + 2 * W_STAGE_B)   // 197888

__device__ __nv_bfloat16 g_Wb[32 * K_DIM];   // bf16 W rows: 0-7 ri, 8-15 wo, 16-31 sm

__device__ __forceinline__ void ffma2(unsigned long long &acc,
                                      unsigned long long a,
                                      unsigned long long b) {
    asm("fma.rn.f32x2 %0, %1, %2, %0;" : "+l"(acc) : "l"(a), "l"(b));
}
__device__ __forceinline__ float hsum2(unsigned long long v) {
    return __uint_as_float((unsigned)(v & 0xffffffffull)) +
           __uint_as_float((unsigned)(v >> 32));
}
__device__ __forceinline__ void cp_async16(uint32_t saddr, const void* g) {
    asm volatile("cp.async.cg.shared.global [%0], [%1], 16;\n" :: "r"(saddr), "l"(g));
}
__device__ __forceinline__ void cp_commit() {
    asm volatile("cp.async.commit_group;\n");
}
template <int N>
__device__ __forceinline__ void cp_wait() {
    asm volatile("cp.async.wait_group %0;\n" :: "n"(N));
}
__device__ __forceinline__ uint32_t cvt_bf2(float lo, float hi) {
    uint32_t r;
    asm("cvt.rn.bf16x2.f32 %0, %1, %2;" : "=r"(r) : "f"(hi), "f"(lo));
    return r;
}
__device__ __forceinline__ void mma_bf16(float &c0, float &c1, float &c2, float &c3,
                                         uint32_t a0, uint32_t a1, uint32_t a2, uint32_t a3,
                                         uint32_t b0, uint32_t b1) {
    asm volatile(
        "mma.sync.aligned.m16n8k16.row.col.f32.bf16.bf16.f32 "
        "{%0,%1,%2,%3}, {%4,%5,%6,%7}, {%8,%9}, {%0,%1,%2,%3};"
        : "+f"(c0), "+f"(c1), "+f"(c2), "+f"(c3)
        : "r"(a0), "r"(a1), "r"(a2), "r"(a3), "r"(b0), "r"(b1));
}

// ---------------------------------------------------------------------------
// prepass: W fp32 -> bf16
// ---------------------------------------------------------------------------
__global__ __launch_bounds__(256)
void wconv(const float* __restrict__ Wri, const float* __restrict__ Wwo,
           const float* __restrict__ Wsm) {
    const int base = (blockIdx.x * 256 + threadIdx.x) * 4;   // grid 128
    const int d = base / K_DIM;
    const int k = base % K_DIM;
    const float* wrow = (d < 8)  ? (Wri + d * K_DIM)
                      : (d < 16) ? (Wwo + (d - 8) * K_DIM)
                                 : (Wsm + (d - 16) * K_DIM);
    const float4 v = *(const float4*)(wrow + k);
    *(uint2*)(&g_Wb[d * K_DIM + k]) = make_uint2(cvt_bf2(v.x, v.y), cvt_bf2(v.z, v.w));
}

// ---------------------------------------------------------------------------
// Fully fused kernel. Grid 2048, block 256 (8 warps). CTA = 8 rows.
// x (fp32) resident in smem for the whole CTA lifetime -> read from DRAM once.
// Phase A: k split across warps; mma bf16 (8 real rows) + fragment sumsq.
// Phase B: cross-warp reduce, 8-thread gates+Sinkhorn -> C in smem.
// Phase C: out = C @ x from smem, streamed stores.
// ---------------------------------------------------------------------------
__global__ __launch_bounds__(256)
void mhc_fused(const float* __restrict__ x, float* __restrict__ out,
               const float* __restrict__ read_in,  const float* __restrict__ a_ri,
               const float* __restrict__ write_out, const float* __restrict__ a_wo,
               const float* __restrict__ stream_mixing, const float* __restrict__ a_sm) {
    extern __shared__ char smc[];
    char* xsm = smc;                        // 8 rows x 16416 B
    char* wsm = smc + X_REGION_B;           // 2 stages x 33280 B

    const int tid  = threadIdx.x;
    const int warp = tid >> 5;              // k-slice owner
    const int lane = tid & 31;
    const int g    = lane >> 2;             // 0..7 (row)
    const int cc   = lane & 3;              // 0..3
    const int row0 = blockIdx.x * ROWS_CTA;

    const uint32_t xbase = (uint32_t)__cvta_generic_to_shared(xsm);
    const uint32_t wbase = (uint32_t)__cvta_generic_to_shared(wsm);

    // per tile: x 8 rows x 128 f4 = 1024 (4/thr); W 32 rows x 64 16B-chunks = 2048 (8/thr)
    auto fetch = [&](int t) {
        const int k0 = t * KT;
#pragma unroll
        for (int i = 0; i < 4; i++) {
            const int f = tid + i * 256;
            const int row = f >> 7, kq = f & 127;
            cp_async16(xbase + row * SXROW_B + (t * 128 + kq) * 16,
                       x + (size_t)(row0 + row) * K_DIM + k0 + kq * 4);
        }
        const uint32_t wst = wbase + (t & 1) * W_STAGE_B;
#pragma unroll
        for (int i = 0; i < 8; i++) {
            const int f = tid + i * 256;
            const int d = f >> 6, kc = f & 63;
            cp_async16(wst + d * SWROW_B + kc * 16,
                       g_Wb + d * K_DIM + k0 + kc * 8);
        }
        cp_commit();
    };

    fetch(0);

    float c[4][4];
#pragma unroll
    for (int n = 0; n < 4; n++)
#pragma unroll
        for (int j = 0; j < 4; j++) c[n][j] = 0.0f;
    unsigned long long ssa = 0ull;

    for (int t = 0; t < NTILES; t++) {
        cp_wait<0>();
        __syncthreads();
        if (t + 1 < NTILES) fetch(t + 1);

        const char* ws = wsm + (t & 1) * W_STAGE_B;
        // warp's k-slice within this tile: [warp*64, warp*64+64)
#pragma unroll
        for (int s = 0; s < 4; s++) {
            const int kl = warp * 64 + s * 16;             // within tile
            const int kf = t * KT + kl;                    // within full row
            const char* arow = xsm + g * SXROW_B + (kf + cc * 2) * 4;
            const float2 fa0 = *(const float2*)(arow);
            const float2 fa2 = *(const float2*)(arow + 32);
            const unsigned long long u0 = *(const unsigned long long*)&fa0;
            const unsigned long long u2 = *(const unsigned long long*)&fa2;
            ffma2(ssa, u0, u0);
            ffma2(ssa, u2, u2);
            const uint32_t a0 = cvt_bf2(fa0.x, fa0.y);
            const uint32_t a2 = cvt_bf2(fa2.x, fa2.y);
#pragma unroll
            for (int ng = 0; ng < 4; ng++) {
                const char* brow = ws + (ng * 8 + g) * SWROW_B + (kl + cc * 2) * 2;
                const uint32_t b0 = *(const uint32_t*)(brow);
                const uint32_t b1 = *(const uint32_t*)(brow + 16);
                mma_bf16(c[ng][0], c[ng][1], c[ng][2], c[ng][3],
                         a0, 0u, a2, 0u, b0, b1);
            }
        }
    }
    __syncthreads();   // all W-stage reads done -> alias reduction scratch there

    float* Hp  = (float*)wsm;               // [8 warps][8 rows][32 dots]
    float* SSp = Hp + 8 * 8 * 32;           // [8 warps][8 rows]
    float* Hs  = SSp + 64;                  // [8][32] reduced
    float* Cs  = Hs + 8 * 32;               // [8][16]

    // write per-warp partials
#pragma unroll
    for (int ng = 0; ng < 4; ng++) {
        const int d0 = ng * 8 + cc * 2;
        Hp[warp * 256 + g * 32 + d0]     = c[ng][0];
        Hp[warp * 256 + g * 32 + d0 + 1] = c[ng][1];
    }
    {
        float va = hsum2(ssa);
        va += __shfl_xor_sync(0xffffffffu, va, 1);
        va += __shfl_xor_sync(0xffffffffu, va, 2);
        if (cc == 0) SSp[warp * 8 + g] = va;
    }
    __syncthreads();

    // reduce partials: 256 threads, one (row, dot) each
    {
        const int r = tid >> 5, d = tid & 31;
        float v = 0.0f;
#pragma unroll
        for (int w = 0; w < 8; w++) v += Hp[w * 256 + r * 32 + d];
        Hs[r * 32 + d] = v;
    }
    __syncthreads();

    // gates + Sinkhorn: one thread per row
    if (tid < ROWS_CTA) {
        const int r = tid;
        float ssum = 0.0f;
#pragma unroll
        for (int w = 0; w < 8; w++) ssum += SSp[w * 8 + r];
        const float s = rsqrtf(ssum * (1.0f / (float)K_DIM) + F_EPS);
        float h[32];
#pragma unroll
        for (int d = 0; d < 32; d++) h[d] = Hs[r * 32 + d] * s;

        const float ari = a_ri[0], awo = a_wo[0], asmix = a_sm[0];
        float riT[2][4], wo[4][2], p[4][4];
#pragma unroll
        for (int n = 0; n < 4; n++)
#pragma unroll
            for (int m = 0; m < 2; m++) {
                const float hri = ari * h[n * 2 + m] + read_in[n * 2 + m];
                riT[m][n] = 1.0f / (1.0f + expf(-hri));
                const float hwo = awo * h[8 + n * 2 + m] + write_out[n * 2 + m];
                wo[n][m] = 2.0f / (1.0f + expf(-hwo));
            }
#pragma unroll
        for (int i = 0; i < 4; i++)
#pragma unroll
            for (int j = 0; j < 4; j++)
                p[i][j] = expf(asmix * h[16 + i * 4 + j] + stream_mixing[i * 4 + j]);

        for (int it = 0; it < 20; it++) {
#pragma unroll
            for (int i = 0; i < 4; i++) {
                const float inv = 1.0f / (p[i][0] + p[i][1] + p[i][2] + p[i][3]);
#pragma unroll
                for (int j = 0; j < 4; j++) p[i][j] *= inv;
            }
#pragma unroll
            for (int j = 0; j < 4; j++) {
                const float inv = 1.0f / (p[0][j] + p[1][j] + p[2][j] + p[3][j]);
#pragma unroll
                for (int i = 0; i < 4; i++) p[i][j] *= inv;
            }
        }
#pragma unroll
        for (int n = 0; n < 4; n++)
#pragma unroll
            for (int j = 0; j < 4; j++)
                Cs[r * 16 + n * 4 + j] =
                    wo[n][0] * riT[0][j] + wo[n][1] * riT[1][j] + p[n][j];
    }
    __syncthreads();

    // ---- phase C: out = C @ x from smem. warp = row, lanes = columns ----
    {
        const int r = warp;
        float cr[4][4];
#pragma unroll
        for (int n = 0; n < 4; n++)
#pragma unroll
            for (int j = 0; j < 4; j++) cr[n][j] = Cs[r * 16 + n * 4 + j];

        const char* xr = xsm + r * SXROW_B;
        float4* orow = (float4*)(out + (size_t)(row0 + r) * K_DIM);

#pragma unroll
        for (int pch = 0; pch < 8; pch++) {
            const int col = pch * 32 + lane;              // f4 index within 256-wide block
            float4 xv[4];
#pragma unroll
            for (int j = 0; j < 4; j++)
                xv[j] = *(const float4*)(xr + (j * 256 + col) * 16);
#pragma unroll
            for (int n = 0; n < 4; n++) {
                float4 o;
                o.x = cr[n][0] * xv[0].x + cr[n][1] * xv[1].x + cr[n][2] * xv[2].x + cr[n][3] * xv[3].x;
                o.y = cr[n][0] * xv[0].y + cr[n][1] * xv[1].y + cr[n][2] * xv[2].y + cr[n][3] * xv[3].y;
                o.z = cr[n][0] * xv[0].z + cr[n][1] * xv[1].z + cr[n][2] * xv[2].z + cr[n][3] * xv[3].z;
                o.w = cr[n][0] * xv[0].w + cr[n][1] * xv[1].w + cr[n][2] * xv[2].w + cr[n][3] * xv[3].w;
                __stcs(&orow[n * 256 + col], o);
            }
        }
    }
}

extern "C" void kernel_launch(void* const* d_in, const int* in_sizes, int n_in,
                              void* d_out, int out_size) {
    const float* x         = (const float*)d_in[0];
    const float* read_in   = (const float*)d_in[1];
    const float* a_ri      = (const float*)d_in[2];
    const float* write_out = (const float*)d_in[3];
    const float* a_wo      = (const float*)d_in[4];
    const float* smix      = (const float*)d_in[5];
    const float* a_sm      = (const float*)d_in[6];
    const float* Wri       = (const float*)d_in[7];
    const float* Wwo       = (const float*)d_in[8];
    const float* Wsm       = (const float*)d_in[9];
    float* out = (float*)d_out;

    wconv<<<128, 256>>>(Wri, Wwo, Wsm);

    cudaFuncSetAttribute(mhc_fused, cudaFuncAttributeMaxDynamicSharedMemorySize,
                         SMEM_B);
    mhc_fused<<<B_TOTAL / ROWS_CTA, 256, SMEM_B>>>(
        x, out, read_in, a_ri, write_out, a_wo, smix, a_sm);
}

// round 7
// speedup vs baseline: 1.8197x; 1.8197x over previous
#include <cuda_runtime.h>
#include <cuda_bf16.h>
#include <cstdint>

#define B_TOTAL  16384
#define K_DIM    4096
#define F_EPS    1.1920929e-07f

#define ROWS_CTA 64
#define KT       128
#define NTILES   (K_DIM / KT)          // 32
// padded smem strides: x rows 136 floats (544B), W rows 136 bf16 (272B)
#define SX_B     544
#define SW_B     272
#define X_STAGE_B (ROWS_CTA * SX_B)    // 34816
#define W_STAGE_B (32 * SW_B)          // 8704
#define STAGE_B   (X_STAGE_B + W_STAGE_B)  // 43520
#define SMEM_B    (2 * STAGE_B)        // 87040 (Hs/SSs/Cs alias stage 0 after k-loop)

__device__ __nv_bfloat16 g_Wb[32 * K_DIM];   // bf16 W, rows: 0-7 ri, 8-15 wo, 16-31 sm

__device__ __forceinline__ void ffma2(unsigned long long &acc,
                                      unsigned long long a,
                                      unsigned long long b) {
    asm("fma.rn.f32x2 %0, %1, %2, %0;" : "+l"(acc) : "l"(a), "l"(b));
}
__device__ __forceinline__ float hsum2(unsigned long long v) {
    return __uint_as_float((unsigned)(v & 0xffffffffull)) +
           __uint_as_float((unsigned)(v >> 32));
}
__device__ __forceinline__ void cp_async16(uint32_t saddr, const void* g) {
    asm volatile("cp.async.cg.shared.global [%0], [%1], 16;\n" :: "r"(saddr), "l"(g));
}
__device__ __forceinline__ void cp_commit() {
    asm volatile("cp.async.commit_group;\n");
}
template <int N>
__device__ __forceinline__ void cp_wait() {
    asm volatile("cp.async.wait_group %0;\n" :: "n"(N));
}
// pack two f32 -> bf16x2 (lo = first arg, hi = second arg)
__device__ __forceinline__ uint32_t cvt_bf2(float lo, float hi) {
    uint32_t r;
    asm("cvt.rn.bf16x2.f32 %0, %1, %2;" : "=r"(r) : "f"(hi), "f"(lo));
    return r;
}
__device__ __forceinline__ void mma_bf16(float &c0, float &c1, float &c2, float &c3,
                                         uint32_t a0, uint32_t a1, uint32_t a2, uint32_t a3,
                                         uint32_t b0, uint32_t b1) {
    asm volatile(
        "mma.sync.aligned.m16n8k16.row.col.f32.bf16.bf16.f32 "
        "{%0,%1,%2,%3}, {%4,%5,%6,%7}, {%8,%9}, {%0,%1,%2,%3};"
        : "+f"(c0), "+f"(c1), "+f"(c2), "+f"(c3)
        : "r"(a0), "r"(a1), "r"(a2), "r"(a3), "r"(b0), "r"(b1));
}

// ---------------------------------------------------------------------------
// prepass: W fp32 -> bf16 into g_Wb
// ---------------------------------------------------------------------------
__global__ __launch_bounds__(256)
void wconv(const float* __restrict__ Wri, const float* __restrict__ Wwo,
           const float* __restrict__ Wsm) {
    const int base = (blockIdx.x * 256 + threadIdx.x) * 4;   // grid 128
    const int d = base / K_DIM;
    const int k = base % K_DIM;
    const float* wrow = (d < 8)  ? (Wri + d * K_DIM)
                      : (d < 16) ? (Wwo + (d - 8) * K_DIM)
                                 : (Wsm + (d - 16) * K_DIM);
    const float4 v = *(const float4*)(wrow + k);
    *(uint2*)(&g_Wb[d * K_DIM + k]) = make_uint2(cvt_bf2(v.x, v.y), cvt_bf2(v.z, v.w));
}

// ---------------------------------------------------------------------------
// Fused: dots (bf16 mma) + fragment sumsq + gates/Sinkhorn + output, one CTA
// per 64 rows. Phase C re-reads x from global — mostly L2 hits (filled by the
// phase-A cp.async of THIS CTA shortly before). out stored with __stcs so the
// write stream does not evict x from L2.
// Grid 256, block 128 (4 warps, 2 CTAs/SM). Warp tile 16 rows x 32 dots.
// ---------------------------------------------------------------------------
__global__ __launch_bounds__(128)
void mhc_fused(const float* __restrict__ x, float* __restrict__ out,
               const float* __restrict__ read_in,  const float* __restrict__ a_ri,
               const float* __restrict__ write_out, const float* __restrict__ a_wo,
               const float* __restrict__ stream_mixing, const float* __restrict__ a_sm) {
    extern __shared__ char smc[];
    const int tid  = threadIdx.x;
    const int warp = tid >> 5;          // row block (16 rows each)
    const int lane = tid & 31;
    const int row0 = blockIdx.x * ROWS_CTA;

    const uint32_t sbase = (uint32_t)__cvta_generic_to_shared(smc);

    // ---- fetch: per tile 2048 x-float4 + 512 W-16B-chunks = 2560 / 128 thr = 20
    auto fetch = [&](int t) {
        const uint32_t st = sbase + (t & 1) * STAGE_B;
        const int k0 = t * KT;
#pragma unroll
        for (int i = 0; i < 20; i++) {
            const int f = tid + i * 128;
            if (f < 2048) {                        // x: 64 rows x 32 quads
                const int row = f >> 5, kq = f & 31;
                cp_async16(st + row * SX_B + kq * 16,
                           x + (size_t)(row0 + row) * K_DIM + k0 + kq * 4);
            } else {                               // W: 32 rows x 16 chunks of 8 bf16
                const int f2 = f - 2048;
                const int d = f2 >> 4, kc = f2 & 15;
                cp_async16(st + X_STAGE_B + d * SW_B + kc * 16,
                           g_Wb + d * K_DIM + k0 + kc * 8);
            }
        }
        cp_commit();
    };

    fetch(0);

    float c[4][4];
#pragma unroll
    for (int n = 0; n < 4; n++)
#pragma unroll
        for (int j = 0; j < 4; j++) c[n][j] = 0.0f;
    unsigned long long ssa = 0ull, ssb = 0ull;   // rows warp*16+g, +8+g

    const int g  = lane >> 2;     // 0..7
    const int cc = lane & 3;      // 0..3

    for (int t = 0; t < NTILES; t++) {
        cp_wait<0>();
        __syncthreads();
        if (t + 1 < NTILES) fetch(t + 1);

        const char* stage = smc + (t & 1) * STAGE_B;
        const char* xs = stage;
        const char* ws = stage + X_STAGE_B;

#pragma unroll
        for (int s = 0; s < 8; s++) {
            const int kb = s * 16;
            const char* arow = xs + (warp * 16 + g) * SX_B + (kb + cc * 2) * 4;
            const float2 fa0 = *(const float2*)(arow);
            const float2 fa1 = *(const float2*)(arow + 8 * SX_B);
            const float2 fa2 = *(const float2*)(arow + 32);
            const float2 fa3 = *(const float2*)(arow + 8 * SX_B + 32);
            const unsigned long long u0 = *(const unsigned long long*)&fa0;
            const unsigned long long u1 = *(const unsigned long long*)&fa1;
            const unsigned long long u2 = *(const unsigned long long*)&fa2;
            const unsigned long long u3 = *(const unsigned long long*)&fa3;
            ffma2(ssa, u0, u0);
            ffma2(ssa, u2, u2);
            ffma2(ssb, u1, u1);
            ffma2(ssb, u3, u3);

            const uint32_t a0 = cvt_bf2(fa0.x, fa0.y);
            const uint32_t a1 = cvt_bf2(fa1.x, fa1.y);
            const uint32_t a2 = cvt_bf2(fa2.x, fa2.y);
            const uint32_t a3 = cvt_bf2(fa3.x, fa3.y);
#pragma unroll
            for (int ng = 0; ng < 4; ng++) {
                const char* brow = ws + (ng * 8 + g) * SW_B + (kb + cc * 2) * 2;
                const uint32_t b0 = *(const uint32_t*)(brow);
                const uint32_t b1 = *(const uint32_t*)(brow + 16);
                mma_bf16(c[ng][0], c[ng][1], c[ng][2], c[ng][3],
                         a0, a1, a2, a3, b0, b1);
            }
        }
    }
    __syncthreads();   // all reads of stage smem done -> safe to alias Hs/SSs/Cs

    float* Hs  = (float*)smc;                    // [64][32]
    float* SSs = (float*)(smc + 64 * 32 * 4);    // [64]
    float* Cs  = SSs + 64;                       // [64][16]

    // write H from accumulators (already k-reduced by mma)
    {
        const int r0l = warp * 16 + g;
#pragma unroll
        for (int ng = 0; ng < 4; ng++) {
            const int d0 = ng * 8 + cc * 2;
            Hs[r0l * 32 + d0]           = c[ng][0];
            Hs[r0l * 32 + d0 + 1]       = c[ng][1];
            Hs[(r0l + 8) * 32 + d0]     = c[ng][2];
            Hs[(r0l + 8) * 32 + d0 + 1] = c[ng][3];
        }
        float va = hsum2(ssa), vb = hsum2(ssb);
        va += __shfl_xor_sync(0xffffffffu, va, 1);
        va += __shfl_xor_sync(0xffffffffu, va, 2);
        vb += __shfl_xor_sync(0xffffffffu, vb, 1);
        vb += __shfl_xor_sync(0xffffffffu, vb, 2);
        if (cc == 0) {
            SSs[r0l]     = va;
            SSs[r0l + 8] = vb;
        }
    }
    __syncthreads();

    // gates + Sinkhorn: one thread per row (64 rows, 128 threads)
    if (tid < ROWS_CTA) {
        const int r = tid;
        const float s = rsqrtf(SSs[r] * (1.0f / (float)K_DIM) + F_EPS);
        float h[32];
#pragma unroll
        for (int d = 0; d < 32; d++) h[d] = Hs[r * 32 + d] * s;

        const float ari = a_ri[0], awo = a_wo[0], asmix = a_sm[0];
        float riT[2][4], wo[4][2], p[4][4];
#pragma unroll
        for (int n = 0; n < 4; n++)
#pragma unroll
            for (int m = 0; m < 2; m++) {
                const float hri = ari * h[n * 2 + m] + read_in[n * 2 + m];
                riT[m][n] = 1.0f / (1.0f + expf(-hri));
                const float hwo = awo * h[8 + n * 2 + m] + write_out[n * 2 + m];
                wo[n][m] = 2.0f / (1.0f + expf(-hwo));
            }
#pragma unroll
        for (int i = 0; i < 4; i++)
#pragma unroll
            for (int j = 0; j < 4; j++)
                p[i][j] = expf(asmix * h[16 + i * 4 + j] + stream_mixing[i * 4 + j]);

        for (int it = 0; it < 20; it++) {
#pragma unroll
            for (int i = 0; i < 4; i++) {
                const float inv = 1.0f / (p[i][0] + p[i][1] + p[i][2] + p[i][3]);
#pragma unroll
                for (int j = 0; j < 4; j++) p[i][j] *= inv;
            }
#pragma unroll
            for (int j = 0; j < 4; j++) {
                const float inv = 1.0f / (p[0][j] + p[1][j] + p[2][j] + p[3][j]);
#pragma unroll
                for (int i = 0; i < 4; i++) p[i][j] *= inv;
            }
        }
#pragma unroll
        for (int n = 0; n < 4; n++)
#pragma unroll
            for (int j = 0; j < 4; j++)
                Cs[r * 16 + n * 4 + j] =
                    wo[n][0] * riT[0][j] + wo[n][1] * riT[1][j] + p[n][j];
    }
    __syncthreads();

    // ---- phase C: out = C @ x, x re-read from global (L2-warm). 4 warps,
    //      each warp handles 16 rows; per row lanes sweep 8 col-chunks.
    for (int rr = 0; rr < 16; rr++) {
        const int r = warp * 16 + rr;
        float cr[4][4];
#pragma unroll
        for (int n = 0; n < 4; n++)
#pragma unroll
            for (int j = 0; j < 4; j++) cr[n][j] = Cs[r * 16 + n * 4 + j];

        const float4* xr = (const float4*)(x + (size_t)(row0 + r) * K_DIM);
        float4* orow = (float4*)(out + (size_t)(row0 + r) * K_DIM);

#pragma unroll
        for (int pch = 0; pch < 8; pch++) {
            const int col = pch * 32 + lane;
            float4 xv[4];
#pragma unroll
            for (int j = 0; j < 4; j++) xv[j] = __ldg(&xr[j * 256 + col]);
#pragma unroll
            for (int n = 0; n < 4; n++) {
                float4 o;
                o.x = cr[n][0] * xv[0].x + cr[n][1] * xv[1].x + cr[n][2] * xv[2].x + cr[n][3] * xv[3].x;
                o.y = cr[n][0] * xv[0].y + cr[n][1] * xv[1].y + cr[n][2] * xv[2].y + cr[n][3] * xv[3].y;
                o.z = cr[n][0] * xv[0].z + cr[n][1] * xv[1].z + cr[n][2] * xv[2].z + cr[n][3] * xv[3].z;
                o.w = cr[n][0] * xv[0].w + cr[n][1] * xv[1].w + cr[n][2] * xv[2].w + cr[n][3] * xv[3].w;
                __stcs(&orow[n * 256 + col], o);
            }
        }
    }
}

extern "C" void kernel_launch(void* const* d_in, const int* in_sizes, int n_in,
                              void* d_out, int out_size) {
    const float* x         = (const float*)d_in[0];
    const float* read_in   = (const float*)d_in[1];
    const float* a_ri      = (const float*)d_in[2];
    const float* write_out = (const float*)d_in[3];
    const float* a_wo      = (const float*)d_in[4];
    const float* smix      = (const float*)d_in[5];
    const float* a_sm      = (const float*)d_in[6];
    const float* Wri       = (const float*)d_in[7];
    const float* Wwo       = (const float*)d_in[8];
    const float* Wsm       = (const float*)d_in[9];
    float* out = (float*)d_out;

    wconv<<<128, 256>>>(Wri, Wwo, Wsm);

    cudaFuncSetAttribute(mhc_fused, cudaFuncAttributeMaxDynamicSharedMemorySize,
                         SMEM_B);
    mhc_fused<<<B_TOTAL / ROWS_CTA, 128, SMEM_B>>>(
        x, out, read_in, a_ri, write_out, a_wo, smix, a_sm);
}

// round 10
// speedup vs baseline: 1.9435x; 1.0681x over previous
#include <cuda_runtime.h>
#include <cuda_bf16.h>
#include <cstdint>

#define B_TOTAL  16384
#define K_DIM    4096
#define F_EPS    1.1920929e-07f

#define ROWS_CTA 64
#define KT       64
#define NTILES   (K_DIM / KT)          // 64
#define STAGES   4
// padded smem strides: x rows 72 floats (288 B ≡ 32 mod 128),
//                      W rows 72 bf16 (144 B ≡ 16 mod 128)
#define SX_B     288
#define SW_B     144
#define X_STAGE_B (ROWS_CTA * SX_B)    // 18432
#define W_STAGE_B (32 * SW_B)          // 4608
#define STAGE_B   (X_STAGE_B + W_STAGE_B)  // 23040
#define SMEM_B    (STAGES * STAGE_B)   // 92160 (Hs/SSs alias stage 0 after k-loop)

__device__ __nv_bfloat16 g_Wb[32 * K_DIM];   // bf16 W, rows: 0-7 ri, 8-15 wo, 16-31 sm
__device__ float g_C[B_TOTAL * 16];          // per-row 4x4 combination matrix

__device__ __forceinline__ void ffma2(unsigned long long &acc,
                                      unsigned long long a,
                                      unsigned long long b) {
    asm("fma.rn.f32x2 %0, %1, %2, %0;" : "+l"(acc) : "l"(a), "l"(b));
}
__device__ __forceinline__ float hsum2(unsigned long long v) {
    return __uint_as_float((unsigned)(v & 0xffffffffull)) +
           __uint_as_float((unsigned)(v >> 32));
}
__device__ __forceinline__ void cp_async16(uint32_t saddr, const void* g) {
    asm volatile("cp.async.cg.shared.global [%0], [%1], 16;\n" :: "r"(saddr), "l"(g));
}
__device__ __forceinline__ void cp_commit() {
    asm volatile("cp.async.commit_group;\n");
}
template <int N>
__device__ __forceinline__ void cp_wait() {
    asm volatile("cp.async.wait_group %0;\n" :: "n"(N));
}
// pack two f32 -> bf16x2 (lo = first arg, hi = second arg)
__device__ __forceinline__ uint32_t cvt_bf2(float lo, float hi) {
    uint32_t r;
    asm("cvt.rn.bf16x2.f32 %0, %1, %2;" : "=r"(r) : "f"(hi), "f"(lo));
    return r;
}
__device__ __forceinline__ void mma_bf16(float &c0, float &c1, float &c2, float &c3,
                                         uint32_t a0, uint32_t a1, uint32_t a2, uint32_t a3,
                                         uint32_t b0, uint32_t b1) {
    asm volatile(
        "mma.sync.aligned.m16n8k16.row.col.f32.bf16.bf16.f32 "
        "{%0,%1,%2,%3}, {%4,%5,%6,%7}, {%8,%9}, {%0,%1,%2,%3};"
        : "+f"(c0), "+f"(c1), "+f"(c2), "+f"(c3)
        : "r"(a0), "r"(a1), "r"(a2), "r"(a3), "r"(b0), "r"(b1));
}

// ---------------------------------------------------------------------------
// prepass: W fp32 -> bf16 into g_Wb
// ---------------------------------------------------------------------------
__global__ __launch_bounds__(256)
void wconv(const float* __restrict__ Wri, const float* __restrict__ Wwo,
           const float* __restrict__ Wsm) {
    const int base = (blockIdx.x * 256 + threadIdx.x) * 4;   // grid 128
    const int d = base / K_DIM;
    const int k = base % K_DIM;
    const float* wrow = (d < 8)  ? (Wri + d * K_DIM)
                      : (d < 16) ? (Wwo + (d - 8) * K_DIM)
                                 : (Wsm + (d - 16) * K_DIM);
    const float4 v = *(const float4*)(wrow + k);
    *(uint2*)(&g_Wb[d * K_DIM + k]) = make_uint2(cvt_bf2(v.x, v.y), cvt_bf2(v.z, v.w));
}

// ---------------------------------------------------------------------------
// K1: dots via bf16 mma + fragment-sumsq + gates/Sinkhorn -> g_C.
// Grid 256, block 128 (4 warps, 2 CTAs/SM). CTA = 64 rows, warp = 16 rows x 32 dots.
// KT=64 k-tiles, 4 smem stages, 3 fetches in flight (wait_group 2).
// ---------------------------------------------------------------------------
__global__ __launch_bounds__(128)
void mhc_dots(const float* __restrict__ x,
              const float* __restrict__ read_in,  const float* __restrict__ a_ri,
              const float* __restrict__ write_out, const float* __restrict__ a_wo,
              const float* __restrict__ stream_mixing, const float* __restrict__ a_sm) {
    extern __shared__ char smc[];
    const int tid  = threadIdx.x;
    const int warp = tid >> 5;          // row block (16 rows each)
    const int lane = tid & 31;
    const int row0 = blockIdx.x * ROWS_CTA;

    const uint32_t sbase = (uint32_t)__cvta_generic_to_shared(smc);

    // per tile: x 64 rows x 16 quads = 1024 f4, W 32 rows x 8 16B-chunks = 256
    // -> 1280 / 128 threads = 10 cp.async each
    auto fetch = [&](int t) {
        const uint32_t st = sbase + (t & (STAGES - 1)) * STAGE_B;
        const int k0 = t * KT;
#pragma unroll
        for (int i = 0; i < 8; i++) {              // x part
            const int f = tid + i * 128;
            const int row = f >> 4, kq = f & 15;
            cp_async16(st + row * SX_B + kq * 16,
                       x + (size_t)(row0 + row) * K_DIM + k0 + kq * 4);
        }
#pragma unroll
        for (int i = 0; i < 2; i++) {              // W part
            const int f2 = tid + i * 128;
            const int d = f2 >> 3, kc = f2 & 7;
            cp_async16(st + X_STAGE_B + d * SW_B + kc * 16,
                       g_Wb + d * K_DIM + k0 + kc * 8);
        }
        cp_commit();
    };

    fetch(0);
    fetch(1);
    fetch(2);

    float c[4][4];
#pragma unroll
    for (int n = 0; n < 4; n++)
#pragma unroll
        for (int j = 0; j < 4; j++) c[n][j] = 0.0f;
    unsigned long long ssa = 0ull, ssb = 0ull;   // rows warp*16+g, +8+g

    const int g  = lane >> 2;     // 0..7
    const int cc = lane & 3;      // 0..3

    for (int t = 0; t < NTILES; t++) {
        cp_wait<STAGES - 2>();   // tile t landed (<=2 younger groups pending)
        __syncthreads();         // all warps past compute(t-1); stage (t+3)%4 free
        if (t + 3 < NTILES) fetch(t + 3);

        const char* stage = smc + (t & (STAGES - 1)) * STAGE_B;
        const char* xs = stage;
        const char* ws = stage + X_STAGE_B;

#pragma unroll
        for (int s = 0; s < 4; s++) {
            const int kb = s * 16;
            const char* arow = xs + (warp * 16 + g) * SX_B + (kb + cc * 2) * 4;
            const float2 fa0 = *(const float2*)(arow);
            const float2 fa1 = *(const float2*)(arow + 8 * SX_B);
            const float2 fa2 = *(const float2*)(arow + 32);
            const float2 fa3 = *(const float2*)(arow + 8 * SX_B + 32);
            const unsigned long long u0 = *(const unsigned long long*)&fa0;
            const unsigned long long u1 = *(const unsigned long long*)&fa1;
            const unsigned long long u2 = *(const unsigned long long*)&fa2;
            const unsigned long long u3 = *(const unsigned long long*)&fa3;
            ffma2(ssa, u0, u0);
            ffma2(ssa, u2, u2);
            ffma2(ssb, u1, u1);
            ffma2(ssb, u3, u3);

            const uint32_t a0 = cvt_bf2(fa0.x, fa0.y);
            const uint32_t a1 = cvt_bf2(fa1.x, fa1.y);
            const uint32_t a2 = cvt_bf2(fa2.x, fa2.y);
            const uint32_t a3 = cvt_bf2(fa3.x, fa3.y);
#pragma unroll
            for (int ng = 0; ng < 4; ng++) {
                const char* brow = ws + (ng * 8 + g) * SW_B + (kb + cc * 2) * 2;
                const uint32_t b0 = *(const uint32_t*)(brow);
                const uint32_t b1 = *(const uint32_t*)(brow + 16);
                mma_bf16(c[ng][0], c[ng][1], c[ng][2], c[ng][3],
                         a0, a1, a2, a3, b0, b1);
            }
        }
    }
    __syncthreads();   // all reads of stage smem done -> safe to alias Hs/SSs

    float* Hs  = (float*)smc;                    // [64][32]
    float* SSs = (float*)(smc + 64 * 32 * 4);    // [64]

    // write H from accumulators (already k-reduced by mma)
    {
        const int r0l = warp * 16 + g;
#pragma unroll
        for (int ng = 0; ng < 4; ng++) {
            const int d0 = ng * 8 + cc * 2;
            Hs[r0l * 32 + d0]           = c[ng][0];
            Hs[r0l * 32 + d0 + 1]       = c[ng][1];
            Hs[(r0l + 8) * 32 + d0]     = c[ng][2];
            Hs[(r0l + 8) * 32 + d0 + 1] = c[ng][3];
        }
        float va = hsum2(ssa), vb = hsum2(ssb);
        va += __shfl_xor_sync(0xffffffffu, va, 1);
        va += __shfl_xor_sync(0xffffffffu, va, 2);
        vb += __shfl_xor_sync(0xffffffffu, vb, 1);
        vb += __shfl_xor_sync(0xffffffffu, vb, 2);
        if (cc == 0) {
            SSs[r0l]     = va;
            SSs[r0l + 8] = vb;
        }
    }
    __syncthreads();

    // gates + Sinkhorn: one thread per row (64 rows, 128 threads)
    if (tid < ROWS_CTA) {
        const int r = tid;
        const float s = rsqrtf(SSs[r] * (1.0f / (float)K_DIM) + F_EPS);
        float h[32];
#pragma unroll
        for (int d = 0; d < 32; d++) h[d] = Hs[r * 32 + d] * s;

        const float ari = a_ri[0], awo = a_wo[0], asmix = a_sm[0];
        float riT[2][4], wo[4][2], p[4][4];
#pragma unroll
        for (int n = 0; n < 4; n++)
#pragma unroll
            for (int m = 0; m < 2; m++) {
                const float hri = ari * h[n * 2 + m] + read_in[n * 2 + m];
                riT[m][n] = 1.0f / (1.0f + expf(-hri));
                const float hwo = awo * h[8 + n * 2 + m] + write_out[n * 2 + m];
                wo[n][m] = 2.0f / (1.0f + expf(-hwo));
            }
#pragma unroll
        for (int i = 0; i < 4; i++)
#pragma unroll
            for (int j = 0; j < 4; j++)
                p[i][j] = expf(asmix * h[16 + i * 4 + j] + stream_mixing[i * 4 + j]);

        for (int it = 0; it < 20; it++) {
#pragma unroll
            for (int i = 0; i < 4; i++) {
                const float inv = 1.0f / (p[i][0] + p[i][1] + p[i][2] + p[i][3]);
#pragma unroll
                for (int j = 0; j < 4; j++) p[i][j] *= inv;
            }
#pragma unroll
            for (int j = 0; j < 4; j++) {
                const float inv = 1.0f / (p[0][j] + p[1][j] + p[2][j] + p[3][j]);
#pragma unroll
                for (int i = 0; i < 4; i++) p[i][j] *= inv;
            }
        }
#pragma unroll
        for (int n = 0; n < 4; n++)
#pragma unroll
            for (int j = 0; j < 4; j++)
                g_C[(size_t)(row0 + r) * 16 + n * 4 + j] =
                    wo[n][0] * riT[0][j] + wo[n][1] * riT[1][j] + p[n][j];
    }
}

// ---------------------------------------------------------------------------
// K2: out[b, n*1024+d] = sum_j C_b[n][j] * x[b, j*1024+d]. One CTA per row.
// Streaming loads/stores (touch-once data; keep L2 clean).
// ---------------------------------------------------------------------------
__global__ __launch_bounds__(256)
void k3_out(const float* __restrict__ x, float* __restrict__ out) {
    const int b = blockIdx.x;
    __shared__ float Cs[16];
    if (threadIdx.x < 16) Cs[threadIdx.x] = g_C[b * 16 + threadIdx.x];
    __syncthreads();

    const int ci = threadIdx.x;
    const float4* xb = (const float4*)(x + (size_t)b * K_DIM);
    float4* ob = (float4*)(out + (size_t)b * K_DIM);

    float4 xv[4];
#pragma unroll
    for (int j = 0; j < 4; j++) xv[j] = __ldcs(&xb[j * 256 + ci]);

#pragma unroll
    for (int n = 0; n < 4; n++) {
        const float c0 = Cs[n * 4 + 0], c1 = Cs[n * 4 + 1],
                    c2 = Cs[n * 4 + 2], c3 = Cs[n * 4 + 3];
        float4 o;
        o.x = c0 * xv[0].x + c1 * xv[1].x + c2 * xv[2].x + c3 * xv[3].x;
        o.y = c0 * xv[0].y + c1 * xv[1].y + c2 * xv[2].y + c3 * xv[3].y;
        o.z = c0 * xv[0].z + c1 * xv[1].z + c2 * xv[2].z + c3 * xv[3].z;
        o.w = c0 * xv[0].w + c1 * xv[1].w + c2 * xv[2].w + c3 * xv[3].w;
        __stcs(&ob[n * 256 + ci], o);
    }
}

extern "C" void kernel_launch(void* const* d_in, const int* in_sizes, int n_in,
                              void* d_out, int out_size) {
    const float* x         = (const float*)d_in[0];
    const float* read_in   = (const float*)d_in[1];
    const float* a_ri      = (const float*)d_in[2];
    const float* write_out = (const float*)d_in[3];
    const float* a_wo      = (const float*)d_in[4];
    const float* smix      = (const float*)d_in[5];
    const float* a_sm      = (const float*)d_in[6];
    const float* Wri       = (const float*)d_in[7];
    const float* Wwo       = (const float*)d_in[8];
    const float* Wsm       = (const float*)d_in[9];
    float* out = (float*)d_out;

    wconv<<<128, 256>>>(Wri, Wwo, Wsm);

    cudaFuncSetAttribute(mhc_dots, cudaFuncAttributeMaxDynamicSharedMemorySize,
                         SMEM_B);
    mhc_dots<<<B_TOTAL / ROWS_CTA, 128, SMEM_B>>>(
        x, read_in, a_ri, write_out, a_wo, smix, a_sm);

    k3_out<<<B_TOTAL, 256>>>(x, out);
}